// round 14
// baseline (speedup 1.0000x reference)
#include <cuda_runtime.h>
#include <cstdint>
#include <cstddef>

#define NN   100000   // nodes (max)
#define HH   96       // hidden
#define AA   32       // attn dim
#define EE   500000   // edges per type (max)
#define PCP2 384      // padded GEMM col count (288 A + 4 attn + pad)

// ---------------- device scratch ----------------------------------------------
__device__ float g_PA[(size_t)NN * 288];        // A0|A1|A2 per row (gathered by agg)
__device__ float g_PE[(size_t)NN * 4];          // el0,er0,el1,er1 (L2-hot gathers)
__device__ float g_WpackT[HH * PCP2];           // k-major: [k][j]
__device__ float g_CB[3 * HH];                  // c_t
__device__ float g_F[3 * HH * HH];              // F_t = WmB_t @ Wu_t  [t][k][j]
__device__ float g_Wu2[384 * HH];               // folded Wu
__device__ float g_cvec[3 * HH];                // c_t @ Wu_t
__device__ float g_w0[EE];
__device__ float g_w1[EE];
__device__ float g_Xm[(size_t)NN * 288];        // [num0/den0 | num1/den1 | sum2/cnt2]
__device__ int   g_deg[3 * NN];
__device__ int   g_start[3 * NN];
__device__ int   g_cur[3 * NN];
__device__ int   g_bsum[128];
__device__ int   g_csr[3 * EE];

// ---------------- packed f32x2 helpers -----------------------------------------
__device__ __forceinline__ unsigned long long pk2(float lo, float hi) {
    unsigned long long r;
    asm("mov.b64 %0, {%1, %2};" : "=l"(r) : "f"(lo), "f"(hi));
    return r;
}
__device__ __forceinline__ void upk2(unsigned long long v, float& lo, float& hi) {
    asm("mov.b64 {%0, %1}, %2;" : "=f"(lo), "=f"(hi) : "l"(v));
}
__device__ __forceinline__ void fma2(unsigned long long& d, unsigned long long a, unsigned long long b) {
    asm("fma.rn.f32x2 %0, %1, %2, %3;" : "=l"(d) : "l"(a), "l"(b), "l"(d));
}
__device__ __forceinline__ void cp_async16(void* smem, const void* gmem) {
    unsigned s = (unsigned)__cvta_generic_to_shared(smem);
    asm volatile("cp.async.cg.shared.global [%0], [%1], 16;" :: "r"(s), "l"(gmem));
}
__device__ __forceinline__ void cp_commit() { asm volatile("cp.async.commit_group;"); }
__device__ __forceinline__ void cp_wait0()  { asm volatile("cp.async.wait_group 0;"); }

// ---------------- 1. fused: zero deg/cur + pack WpackT + pack CB ----------------
__global__ void pack_all_kernel(const float* __restrict__ Wm0, const float* __restrict__ bm0,
                                const float* __restrict__ ef0,
                                const float* __restrict__ Wm1, const float* __restrict__ bm1,
                                const float* __restrict__ ef1,
                                const float* __restrict__ Wm2, const float* __restrict__ bm2,
                                const float* __restrict__ ef2,
                                const float* __restrict__ Wn0, const float* __restrict__ Wa0,
                                const float* __restrict__ Wn1, const float* __restrict__ Wa1,
                                int Nn) {
    int gid = blockIdx.x * blockDim.x + threadIdx.x;
    int M3 = 3 * Nn;
    if (gid < M3) { g_deg[gid] = 0; g_cur[gid] = 0; return; }
    gid -= M3;
    if (gid < PCP2 * HH) {
        int j = gid / HH;     // output column
        int k = gid % HH;     // input feature
        float v = 0.f;
        if (j < 288) {                      // A-blocks: src part of Wm
            int t = j / HH;
            int jj = j % HH;
            const float* Wm = (t == 0) ? Wm0 : (t == 1) ? Wm1 : Wm2;
            v = Wm[(size_t)k * HH + jj];
        } else if (j < 292) {               // attn: el0,er0,el1,er1
            int q = j - 288;
            const float* Wn = (q < 2) ? Wn0 : Wn1;
            const float* Wa = (q < 2) ? Wa0 : Wa1;
            int off = (q & 1) * AA;
            float s = 0.f;
            #pragma unroll
            for (int a = 0; a < AA; a++) s += Wn[(size_t)k * AA + a] * Wa[off + a];
            v = s;
        }
        g_WpackT[(size_t)k * PCP2 + j] = v;
        return;
    }
    gid -= PCP2 * HH;
    if (gid < 3 * HH) {
        int t = gid / HH, j = gid % HH;
        const float* Wm = (t == 0) ? Wm0 : (t == 1) ? Wm1 : Wm2;
        const float* bm = (t == 0) ? bm0 : (t == 1) ? bm1 : bm2;
        const float* ef = (t == 0) ? ef0 : (t == 1) ? ef1 : ef2;
        float s = bm[j];
        #pragma unroll
        for (int d = 0; d < 16; d++) s += ef[d] * Wm[(size_t)(192 + d) * HH + j];
        g_CB[gid] = s;
    }
}

// ---------------- 2. degrees, all 3 types in one launch -------------------------
__global__ void deg_all_kernel(const int* __restrict__ dst0, const int* __restrict__ dst1,
                               const int* __restrict__ dst2, int E0, int E1, int E2, int Nn) {
    int e = blockIdx.x * blockDim.x + threadIdx.x;
    if (e < E0) { atomicAdd(&g_deg[dst0[e]], 1); return; }
    e -= E0;
    if (e < E1) { atomicAdd(&g_deg[Nn + dst1[e]], 1); return; }
    e -= E1;
    if (e < E2) { atomicAdd(&g_deg[2 * Nn + dst2[e]], 1); }
}

// ---------------- 3. block scan (4096 elems/block) ------------------------------
__global__ void scan_blocks_kernel(int M) {
    __shared__ int s[256];
    int base = blockIdx.x * 4096;
    int tid = threadIdx.x;
    int vals[16];
    int sum = 0;
    #pragma unroll
    for (int i = 0; i < 16; i++) {
        int idx = base + tid * 16 + i;
        int v = (idx < M) ? g_deg[idx] : 0;
        vals[i] = sum;
        sum += v;
    }
    s[tid] = sum;
    __syncthreads();
    #pragma unroll
    for (int off = 1; off < 256; off <<= 1) {
        int t = (tid >= off) ? s[tid - off] : 0;
        __syncthreads();
        if (tid >= off) s[tid] += t;
        __syncthreads();
    }
    int excl = (tid > 0) ? s[tid - 1] : 0;
    #pragma unroll
    for (int i = 0; i < 16; i++) {
        int idx = base + tid * 16 + i;
        if (idx < M) g_start[idx] = excl + vals[i];
    }
    if (tid == 0) g_bsum[blockIdx.x] = s[255];
}

// ---------------- 4. GEMM 1: [PA|PE] = h @ Wcat  (launch #4 -> ncu target) -----
__global__ void __launch_bounds__(256) gemm_p_kernel(const float* __restrict__ h, int Nn) {
    __shared__ float As[2][16][132];
    __shared__ float Bs[2][16][132];
    const int bm = blockIdx.y * 128;
    const int bn = blockIdx.x * 128;
    const int tid = threadIdx.x;
    const int tr = (tid >> 4) << 2;
    const int tc = (tid & 15) << 2;
    unsigned long long acc[8][4];
    #pragma unroll
    for (int i = 0; i < 8; i++)
        #pragma unroll
        for (int j = 0; j < 4; j++) acc[i][j] = 0ull;

    float4 pa[2];
    #pragma unroll
    for (int it = 0; it < 2; it++) {
        int q = tid + it * 256;
        int k = q >> 5;
        int c4 = (q & 31) << 2;
        cp_async16(&Bs[0][k][c4], &g_WpackT[(size_t)k * PCP2 + bn + c4]);
    }
    cp_commit();
    #pragma unroll
    for (int it = 0; it < 2; it++) {
        int q = tid + it * 256;
        int row = q >> 2, kq = (q & 3) << 2;
        int grow = bm + row;
        pa[it] = (grow < Nn) ? *reinterpret_cast<const float4*>(&h[(size_t)grow * HH + kq])
                             : make_float4(0.f, 0.f, 0.f, 0.f);
    }
    #pragma unroll
    for (int it = 0; it < 2; it++) {
        int q = tid + it * 256;
        int row = q >> 2, kq = (q & 3) << 2;
        As[0][kq + 0][row] = pa[it].x; As[0][kq + 1][row] = pa[it].y;
        As[0][kq + 2][row] = pa[it].z; As[0][kq + 3][row] = pa[it].w;
    }
    cp_wait0();
    __syncthreads();

    int b = 0;
    for (int k0 = 0; k0 < HH; k0 += 16) {
        bool more = (k0 + 16 < HH);
        if (more) {
            #pragma unroll
            for (int it = 0; it < 2; it++) {
                int q = tid + it * 256;
                int k = q >> 5;
                int c4 = (q & 31) << 2;
                cp_async16(&Bs[b ^ 1][k][c4], &g_WpackT[(size_t)(k0 + 16 + k) * PCP2 + bn + c4]);
            }
            cp_commit();
            #pragma unroll
            for (int it = 0; it < 2; it++) {
                int q = tid + it * 256;
                int row = q >> 2, kq = (q & 3) << 2;
                int grow = bm + row;
                pa[it] = (grow < Nn) ? *reinterpret_cast<const float4*>(&h[(size_t)grow * HH + k0 + 16 + kq])
                                     : make_float4(0.f, 0.f, 0.f, 0.f);
            }
        }
        #pragma unroll
        for (int kk = 0; kk < 16; kk++) {
            float4 a0 = *reinterpret_cast<const float4*>(&As[b][kk][tr]);
            float4 a1 = *reinterpret_cast<const float4*>(&As[b][kk][tr + 64]);
            float4 b0 = *reinterpret_cast<const float4*>(&Bs[b][kk][tc]);
            float4 b1 = *reinterpret_cast<const float4*>(&Bs[b][kk][tc + 64]);
            unsigned long long bb[4] = {pk2(b0.x, b0.y), pk2(b0.z, b0.w),
                                        pk2(b1.x, b1.y), pk2(b1.z, b1.w)};
            float aa[8] = {a0.x, a0.y, a0.z, a0.w, a1.x, a1.y, a1.z, a1.w};
            #pragma unroll
            for (int i = 0; i < 8; i++) {
                unsigned long long ar = pk2(aa[i], aa[i]);
                #pragma unroll
                for (int j = 0; j < 4; j++) fma2(acc[i][j], ar, bb[j]);
            }
        }
        if (more) {
            #pragma unroll
            for (int it = 0; it < 2; it++) {
                int q = tid + it * 256;
                int row = q >> 2, kq = (q & 3) << 2;
                As[b ^ 1][kq + 0][row] = pa[it].x; As[b ^ 1][kq + 1][row] = pa[it].y;
                As[b ^ 1][kq + 2][row] = pa[it].z; As[b ^ 1][kq + 3][row] = pa[it].w;
            }
            cp_wait0();
        }
        __syncthreads();
        b ^= 1;
    }

    // epilogue: cols [0,288) -> PA, col 288 float4 -> PE, rest padding (dropped)
    #pragma unroll
    for (int i = 0; i < 8; i++) {
        int row = bm + ((i < 4) ? (tr + i) : (tr + 64 + i - 4));
        if (row >= Nn) continue;
        #pragma unroll
        for (int half = 0; half < 2; half++) {
            int colbase = bn + tc + half * 64;
            float4 v;
            upk2(acc[i][half * 2 + 0], v.x, v.y);
            upk2(acc[i][half * 2 + 1], v.z, v.w);
            if (colbase < 288) {
                *reinterpret_cast<float4*>(&g_PA[(size_t)row * 288 + colbase]) = v;
            } else if (colbase == 288) {
                *reinterpret_cast<float4*>(&g_PE[(size_t)row * 4]) = v;
            }
        }
    }
}

// ---------------- 5/6. scan finish ---------------------------------------------
__global__ void scan_tops_kernel(int B) {
    __shared__ int s[128];
    int tid = threadIdx.x;
    s[tid] = (tid < B) ? g_bsum[tid] : 0;
    __syncthreads();
    #pragma unroll
    for (int off = 1; off < 128; off <<= 1) {
        int t = (tid >= off) ? s[tid - off] : 0;
        __syncthreads();
        if (tid >= off) s[tid] += t;
        __syncthreads();
    }
    if (tid < B) g_bsum[tid] = (tid > 0) ? s[tid - 1] : 0;
}

__global__ void scan_add_kernel(int M) {
    int i = blockIdx.x * blockDim.x + threadIdx.x;
    if (i >= M) return;
    g_start[i] += g_bsum[i >> 12];
}

// ---------------- 7. CSR fill, all 3 types --------------------------------------
__global__ void fill_all_kernel(const int* __restrict__ dst0, const int* __restrict__ dst1,
                                const int* __restrict__ dst2, int E0, int E1, int E2, int Nn) {
    int e = blockIdx.x * blockDim.x + threadIdx.x;
    int d, eid;
    if (e < E0) { d = dst0[e]; eid = e; }
    else if (e < E0 + E1) { eid = e - E0; d = Nn + dst1[eid]; }
    else if (e < E0 + E1 + E2) { eid = e - E0 - E1; d = 2 * Nn + dst2[eid]; }
    else return;
    int pos = atomicAdd(&g_cur[d], 1);
    g_csr[g_start[d] + pos] = eid;
}

// ---------------- 8. F_t[k][j] (one (t,k) row per block) ------------------------
__global__ void fold_F_kernel(const float* __restrict__ Wm0, const float* __restrict__ Wm1,
                              const float* __restrict__ Wm2, const float* __restrict__ Wu) {
    int bk = blockIdx.x;          // t*HH + k
    int t = bk / HH, k = bk % HH;
    int j = threadIdx.x;
    const float* Wm = (t == 0) ? Wm0 : (t == 1) ? Wm1 : Wm2;
    const float* wrow = &Wm[(size_t)(HH + k) * HH];
    const float* wu   = &Wu[(size_t)(HH + HH * t) * HH];
    float s = 0.f;
    #pragma unroll 8
    for (int m = 0; m < HH; m++)
        s += wrow[m] * wu[(size_t)m * HH + j];
    g_F[(size_t)t * HH * HH + (size_t)k * HH + j] = s;
}

// ---------------- 9. Wu2 + cvec -------------------------------------------------
__global__ void fold_misc_kernel(const float* __restrict__ Wu) {
    int gid = blockIdx.x * blockDim.x + threadIdx.x;
    if (gid < 384 * HH) {
        int k = gid / HH, j = gid % HH;
        float v = Wu[gid];
        if (k < HH)
            v += g_F[k * HH + j] + g_F[HH * HH + k * HH + j] + g_F[2 * HH * HH + k * HH + j];
        g_Wu2[gid] = v;
    } else if (gid < 384 * HH + 3 * HH) {
        int q = gid - 384 * HH;
        int t = q / HH, j = q % HH;
        float s = 0.f;
        #pragma unroll 8
        for (int m = 0; m < HH; m++)
            s += g_CB[t * HH + m] * Wu[(size_t)(HH + HH * t + m) * HH + j];
        g_cvec[q] = s;
    }
}

// ---------------- 10. edge weights, both attention types ------------------------
__global__ void edge_w_all_kernel(const int* __restrict__ src0, const int* __restrict__ dst0,
                                  const int* __restrict__ src1, const int* __restrict__ dst1,
                                  int E0, int E1) {
    int e = blockIdx.x * blockDim.x + threadIdx.x;
    if (e < E0) {
        int s = src0[e], d = dst0[e];
        float sc = __ldg(&g_PE[(size_t)s * 4 + 0]) + __ldg(&g_PE[(size_t)d * 4 + 1]);
        sc = (sc > 0.f) ? sc : 0.01f * sc;
        g_w0[e] = expf(sc);
    } else if (e < E0 + E1) {
        int eid = e - E0;
        int s = src1[eid], d = dst1[eid];
        float sc = __ldg(&g_PE[(size_t)s * 4 + 2]) + __ldg(&g_PE[(size_t)d * 4 + 3]);
        sc = (sc > 0.f) ? sc : 0.01f * sc;
        g_w1[eid] = expf(sc);
    }
}

// ---------------- 11. dst-parallel aggregation (2-deep pipeline) ----------------
__global__ void agg_kernel(const int* __restrict__ src0, const int* __restrict__ src1,
                           const int* __restrict__ src2, int Nn) {
    int gid = blockIdx.x * blockDim.x + threadIdx.x;
    int g = gid / 24;
    int c = gid % 24;
    if (g >= 3 * Nn) return;
    int t = g / Nn;
    int n = g - t * Nn;
    int start = g_start[g];
    int cnt = g_deg[g];
    const int* src = (t == 0) ? src0 : (t == 1) ? src1 : src2;
    const float* wb = (t == 0) ? g_w0 : g_w1;   // unused for t==2
    int toff = t * HH;
    int c4 = c << 2;

    float4 acc = make_float4(0.f, 0.f, 0.f, 0.f);
    float den = 0.f;

    // software pipeline: indices two ahead, payload (a,w) one ahead
    int e0 = 0, s0 = 0, e1 = 0, s1 = 0;
    float4 a0 = make_float4(0.f, 0.f, 0.f, 0.f);
    float w0 = 0.f;
    if (cnt > 0) {
        e0 = __ldg(&g_csr[start]);
        s0 = __ldg(&src[e0]);
        if (cnt > 1) { e1 = __ldg(&g_csr[start + 1]); s1 = __ldg(&src[e1]); }
        a0 = *reinterpret_cast<const float4*>(&g_PA[(size_t)s0 * 288 + toff + c4]);
        w0 = (t < 2) ? __ldg(&wb[e0]) : 1.f;
    }
    for (int i = 0; i < cnt; i++) {
        int e2 = 0, s2 = 0;
        if (i + 2 < cnt) { e2 = __ldg(&g_csr[start + i + 2]); s2 = __ldg(&src[e2]); }
        float4 a1 = make_float4(0.f, 0.f, 0.f, 0.f);
        float w1 = 0.f;
        if (i + 1 < cnt) {
            a1 = *reinterpret_cast<const float4*>(&g_PA[(size_t)s1 * 288 + toff + c4]);
            w1 = (t < 2) ? __ldg(&wb[e1]) : 1.f;
        }
        acc.x += w0 * a0.x; acc.y += w0 * a0.y; acc.z += w0 * a0.z; acc.w += w0 * a0.w;
        den += w0;
        e1 = e2; s1 = s2; a0 = a1; w0 = w1;
    }

    float4 outv = make_float4(0.f, 0.f, 0.f, 0.f);
    if (cnt > 0) {
        float r = 1.f / den;
        outv = make_float4(acc.x * r, acc.y * r, acc.z * r, acc.w * r);
    }
    *reinterpret_cast<float4*>(&g_Xm[(size_t)n * 288 + toff + c4]) = outv;
}

// ---------------- 12. GEMM 2: out = relu([h|Xm] @ Wu2 + bu + Σcvec) ------------
__global__ void __launch_bounds__(256) gemm_out_kernel(const float* __restrict__ h,
                                                       const float* __restrict__ bu,
                                                       float* __restrict__ out, int Nn) {
    __shared__ float As[2][16][132];
    __shared__ float Bs[2][16][100];
    const int bm = blockIdx.x * 128;
    const int tid = threadIdx.x;
    const int tr = (tid >> 4) << 2;
    const int tc = (tid & 15) * 6;
    unsigned long long acc[8][3];
    #pragma unroll
    for (int i = 0; i < 8; i++)
        #pragma unroll
        for (int j = 0; j < 3; j++) acc[i][j] = 0ull;

    float4 pa[2];
    #pragma unroll
    for (int it = 0; it < 2; it++) {
        int q = tid + it * 256;
        if (q < 384) {
            int k = q / 24;
            int c4 = (q % 24) << 2;
            cp_async16(&Bs[0][k][c4], &g_Wu2[(size_t)k * HH + c4]);
        }
    }
    cp_commit();
    #pragma unroll
    for (int it = 0; it < 2; it++) {
        int q = tid + it * 256;
        int row = q >> 2, kq = (q & 3) << 2;
        int grow = bm + row;
        pa[it] = (grow < Nn) ? *reinterpret_cast<const float4*>(&h[(size_t)grow * HH + kq])
                             : make_float4(0.f, 0.f, 0.f, 0.f);
    }
    #pragma unroll
    for (int it = 0; it < 2; it++) {
        int q = tid + it * 256;
        int row = q >> 2, kq = (q & 3) << 2;
        As[0][kq + 0][row] = pa[it].x; As[0][kq + 1][row] = pa[it].y;
        As[0][kq + 2][row] = pa[it].z; As[0][kq + 3][row] = pa[it].w;
    }
    cp_wait0();
    __syncthreads();

    int b = 0;
    for (int k0 = 0; k0 < 384; k0 += 16) {
        bool more = (k0 + 16 < 384);
        if (more) {
            #pragma unroll
            for (int it = 0; it < 2; it++) {
                int q = tid + it * 256;
                if (q < 384) {
                    int k = q / 24;
                    int c4 = (q % 24) << 2;
                    cp_async16(&Bs[b ^ 1][k][c4], &g_Wu2[(size_t)(k0 + 16 + k) * HH + c4]);
                }
            }
            cp_commit();
            #pragma unroll
            for (int it = 0; it < 2; it++) {
                int q = tid + it * 256;
                int row = q >> 2, kq = (q & 3) << 2;
                int grow = bm + row;
                int col = k0 + 16 + kq;
                float4 v = make_float4(0.f, 0.f, 0.f, 0.f);
                if (grow < Nn) {
                    v = (col < HH)
                      ? *reinterpret_cast<const float4*>(&h[(size_t)grow * HH + col])
                      : *reinterpret_cast<const float4*>(&g_Xm[(size_t)grow * 288 + col - HH]);
                }
                pa[it] = v;
            }
        }
        #pragma unroll
        for (int kk = 0; kk < 16; kk++) {
            float4 a0 = *reinterpret_cast<const float4*>(&As[b][kk][tr]);
            float4 a1 = *reinterpret_cast<const float4*>(&As[b][kk][tr + 64]);
            float2 b0 = *reinterpret_cast<const float2*>(&Bs[b][kk][tc]);
            float2 b1 = *reinterpret_cast<const float2*>(&Bs[b][kk][tc + 2]);
            float2 b2 = *reinterpret_cast<const float2*>(&Bs[b][kk][tc + 4]);
            unsigned long long bb[3] = {pk2(b0.x, b0.y), pk2(b1.x, b1.y), pk2(b2.x, b2.y)};
            float aa[8] = {a0.x, a0.y, a0.z, a0.w, a1.x, a1.y, a1.z, a1.w};
            #pragma unroll
            for (int i = 0; i < 8; i++) {
                unsigned long long ar = pk2(aa[i], aa[i]);
                #pragma unroll
                for (int j = 0; j < 3; j++) fma2(acc[i][j], ar, bb[j]);
            }
        }
        if (more) {
            #pragma unroll
            for (int it = 0; it < 2; it++) {
                int q = tid + it * 256;
                int row = q >> 2, kq = (q & 3) << 2;
                As[b ^ 1][kq + 0][row] = pa[it].x; As[b ^ 1][kq + 1][row] = pa[it].y;
                As[b ^ 1][kq + 2][row] = pa[it].z; As[b ^ 1][kq + 3][row] = pa[it].w;
            }
            cp_wait0();
        }
        __syncthreads();
        b ^= 1;
    }

    float bias[6];
    #pragma unroll
    for (int j = 0; j < 6; j++)
        bias[j] = __ldg(&bu[tc + j]) + g_cvec[tc + j] + g_cvec[HH + tc + j] + g_cvec[2 * HH + tc + j];

    #pragma unroll
    for (int i = 0; i < 8; i++) {
        int row = bm + ((i < 4) ? (tr + i) : (tr + 64 + i - 4));
        if (row >= Nn) continue;
        float v[6];
        upk2(acc[i][0], v[0], v[1]);
        upk2(acc[i][1], v[2], v[3]);
        upk2(acc[i][2], v[4], v[5]);
        #pragma unroll
        for (int j = 0; j < 6; j++) v[j] += bias[j];

        // rare correction: for types with deg==0 the fold added h@F_t + cvec_t; remove it
        int d0 = g_deg[row], d1 = g_deg[Nn + row], d2 = g_deg[2 * Nn + row];
        if ((d0 == 0) || (d1 == 0) || (d2 == 0)) {
            for (int t = 0; t < 3; t++) {
                int dt = (t == 0) ? d0 : (t == 1) ? d1 : d2;
                if (dt != 0) continue;
                const float* Ft = &g_F[t * HH * HH];
                for (int k = 0; k < HH; k++) {
                    float hv = h[(size_t)row * HH + k];
                    #pragma unroll
                    for (int j = 0; j < 6; j++) v[j] -= hv * Ft[k * HH + tc + j];
                }
                #pragma unroll
                for (int j = 0; j < 6; j++) v[j] -= g_cvec[t * HH + tc + j];
            }
        }

        #pragma unroll
        for (int j = 0; j < 6; j++)
            out[(size_t)row * HH + tc + j] = fmaxf(v[j], 0.f);
    }
}

// ---------------- launch -------------------------------------------------------
extern "C" void kernel_launch(void* const* d_in, const int* in_sizes, int n_in,
                              void* d_out, int out_size) {
    const float* h    = (const float*)d_in[0];
    const int*   src0 = (const int*)d_in[1];
    const int*   dst0 = (const int*)d_in[2];
    const int*   src1 = (const int*)d_in[3];
    const int*   dst1 = (const int*)d_in[4];
    const int*   src2 = (const int*)d_in[5];
    const int*   dst2 = (const int*)d_in[6];
    const float* Wm0  = (const float*)d_in[7];
    const float* bm0  = (const float*)d_in[8];
    const float* ef0  = (const float*)d_in[9];
    const float* Wm1  = (const float*)d_in[10];
    const float* bm1  = (const float*)d_in[11];
    const float* ef1  = (const float*)d_in[12];
    const float* Wm2  = (const float*)d_in[13];
    const float* bm2  = (const float*)d_in[14];
    const float* ef2  = (const float*)d_in[15];
    const float* Wn0  = (const float*)d_in[16];
    const float* Wa0  = (const float*)d_in[17];
    const float* Wn1  = (const float*)d_in[18];
    const float* Wa1  = (const float*)d_in[19];
    const float* Wu   = (const float*)d_in[20];
    const float* bu   = (const float*)d_in[21];
    float* out = (float*)d_out;

    int Nn = in_sizes[0] / HH;
    int E0 = in_sizes[1];
    int E1 = in_sizes[3];
    int E2 = in_sizes[5];
    int M3 = 3 * Nn;
    int B = (M3 + 4095) / 4096;
    int Etot = E0 + E1 + E2;

    // 1: fused zero + pack
    int packN = M3 + PCP2 * HH + 3 * HH;
    pack_all_kernel<<<(packN + 255) / 256, 256>>>(Wm0, bm0, ef0, Wm1, bm1, ef1,
                                                  Wm2, bm2, ef2, Wn0, Wa0, Wn1, Wa1, Nn);
    // 2-3: degrees + block scan
    deg_all_kernel<<<(Etot + 255) / 256, 256>>>(dst0, dst1, dst2, E0, E1, E2, Nn);
    scan_blocks_kernel<<<B, 256>>>(M3);

    // 4: the big GEMM (ncu capture slot)
    dim3 g1(PCP2 / 128, (Nn + 127) / 128);
    gemm_p_kernel<<<g1, 256>>>(h, Nn);

    // 5-7: finish scan, fill CSR
    scan_tops_kernel<<<1, 128>>>(B);
    scan_add_kernel<<<(M3 + 255) / 256, 256>>>(M3);
    fill_all_kernel<<<(Etot + 255) / 256, 256>>>(dst0, dst1, dst2, E0, E1, E2, Nn);

    // 8-9: weight folds (needed only by gemm_out)
    fold_F_kernel<<<3 * HH, HH>>>(Wm0, Wm1, Wm2, Wu);
    fold_misc_kernel<<<(384 * HH + 3 * HH + 255) / 256, 256>>>(Wu);

    // 10-12: edge weights, aggregation, output GEMM
    edge_w_all_kernel<<<(E0 + E1 + 255) / 256, 256>>>(src0, dst0, src1, dst1, E0, E1);
    agg_kernel<<<(3 * Nn * 24 + 255) / 256, 256>>>(src0, src1, src2, Nn);
    gemm_out_kernel<<<(Nn + 127) / 128, 256>>>(h, bu, out, Nn);
}